// round 1
// baseline (speedup 1.0000x reference)
#include <cuda_runtime.h>

#define N_TOK   32768
#define NBATCH  64
#define NPER    512
#define DQK     128
#define MF      256
#define DV      256

#define INV_D4      0.29730177875068026f  /* 128^-0.25 */
#define INV_SQRT_M  0.0625f               /* 1/sqrt(256) */
#define EPS_PHI     1e-4f
#define EPS_NORM    1e-8f

// ---------------- scratch (static device memory; no allocations) ----------------
__device__ float    g_Qp[N_TOK * MF];          // 33.6 MB
__device__ float    g_Kp[N_TOK * MF];          // 33.6 MB (Kp0 then scaled in-place)
__device__ float    g_rowmax[N_TOK];
__device__ unsigned g_segmax[NBATCH];          // order-encoded float max
__device__ float    g_KsumP[NBATCH * 4 * MF];  // 4 deterministic partials per batch
__device__ float    g_KV[NBATCH * MF * DV];    // 16.8 MB
__device__ float    g_norm[N_TOK];

// ---------------- helpers ----------------
__device__ __forceinline__ unsigned f2o(float f) {
    unsigned u = __float_as_uint(f);
    return (u & 0x80000000u) ? ~u : (u | 0x80000000u);
}
__device__ __forceinline__ float o2f(unsigned u) {
    return (u & 0x80000000u) ? __uint_as_float(u & 0x7fffffffu)
                             : __uint_as_float(~u);
}

// Packed dual-FMA (Blackwell f32x2) — 2 fp32 FMAs per instruction slot.
__device__ __forceinline__ void ffma2(float2& d, const float2 a, const float2 b) {
    asm("{\n\t"
        ".reg .b64 ra, rb, rd;\n\t"
        "mov.b64 ra, {%2, %3};\n\t"
        "mov.b64 rb, {%4, %5};\n\t"
        "mov.b64 rd, {%0, %1};\n\t"
        "fma.rn.f32x2 rd, ra, rb, rd;\n\t"
        "mov.b64 {%0, %1}, rd;\n\t"
        "}"
        : "+f"(d.x), "+f"(d.y)
        : "f"(a.x), "f"(a.y), "f"(b.x), "f"(b.y));
}

__device__ __forceinline__ float warpMax(float v) {
#pragma unroll
    for (int o = 16; o > 0; o >>= 1) v = fmaxf(v, __shfl_xor_sync(0xffffffffu, v, o));
    return v;
}
__device__ __forceinline__ float warpSum(float v) {
#pragma unroll
    for (int o = 16; o > 0; o >>= 1) v += __shfl_xor_sync(0xffffffffu, v, o);
    return v;
}

// ---------------- init ----------------
__global__ void init_kernel() {
    if (threadIdx.x < NBATCH) g_segmax[threadIdx.x] = 0u;  // 0 == "-inf" in f2o order
}

// ---------------- phi: U = (X*INV_D4)@omega, h, rowmax, exp ----------------
// Block: 256 thr, tile 64 rows x 256 cols (full feature width), K-chunks of 32.
// Thread (ty,tx): rows ty*8..+7, cols {tx*4..+3, 128+tx*4..+3}.
template <int ISQ>
__global__ __launch_bounds__(256)
void phi_kernel(const float* __restrict__ X, const float* __restrict__ omega)
{
    __shared__ float As[64 * 32];    // [row][k]
    __shared__ float Bs[32 * 256];   // [k][col]
    __shared__ float s_wmax[8];

    const int tid = threadIdx.x;
    const int ty  = tid >> 5;
    const int tx  = tid & 31;
    const int row0 = blockIdx.x * 64;

    float2 acc[8][4];
#pragma unroll
    for (int i = 0; i < 8; i++)
#pragma unroll
        for (int g = 0; g < 4; g++) acc[i][g] = make_float2(0.f, 0.f);
    float2 hacc[4];
#pragma unroll
    for (int j = 0; j < 4; j++) hacc[j] = make_float2(0.f, 0.f);

    for (int k0 = 0; k0 < DQK; k0 += 32) {
#pragma unroll
        for (int s = 0; s < 2; s++) {
            int idx = tid + s * 256;
            int r = idx >> 3, c4 = idx & 7;
            float4 v = *(const float4*)(X + (size_t)(row0 + r) * DQK + k0 + c4 * 4);
            v.x *= INV_D4; v.y *= INV_D4; v.z *= INV_D4; v.w *= INV_D4;
            *(float4*)(As + r * 32 + c4 * 4) = v;
        }
#pragma unroll
        for (int s = 0; s < 8; s++) {
            int idx = tid + s * 256;
            int r = idx >> 6, c4 = idx & 63;
            *(float4*)(Bs + r * 256 + c4 * 4) =
                *(const float4*)(omega + (size_t)(k0 + r) * 256 + c4 * 4);
        }
        __syncthreads();
#pragma unroll 4
        for (int kk = 0; kk < 32; kk++) {
            float a[8];
#pragma unroll
            for (int i = 0; i < 8; i++) a[i] = As[(ty * 8 + i) * 32 + kk];
#pragma unroll
            for (int j = 0; j < 4; j++) {
                float2 p = make_float2(a[2 * j], a[2 * j + 1]);
                ffma2(hacc[j], p, p);           // h accumulation (scaled-X sumsq)
            }
            float4 b0 = *(const float4*)(Bs + kk * 256 + tx * 4);
            float4 b1 = *(const float4*)(Bs + kk * 256 + 128 + tx * 4);
#pragma unroll
            for (int i = 0; i < 8; i++) {
                float2 aa = make_float2(a[i], a[i]);
                ffma2(acc[i][0], aa, make_float2(b0.x, b0.y));
                ffma2(acc[i][1], aa, make_float2(b0.z, b0.w));
                ffma2(acc[i][2], aa, make_float2(b1.x, b1.y));
                ffma2(acc[i][3], aa, make_float2(b1.z, b1.w));
            }
        }
        __syncthreads();
    }

    float* Out = ISQ ? g_Qp : g_Kp;
    float blockmax = -3.0e38f;
#pragma unroll
    for (int i = 0; i < 8; i++) {
        int row = row0 + ty * 8 + i;
        float mx = fmaxf(fmaxf(fmaxf(acc[i][0].x, acc[i][0].y), fmaxf(acc[i][1].x, acc[i][1].y)),
                         fmaxf(fmaxf(acc[i][2].x, acc[i][2].y), fmaxf(acc[i][3].x, acc[i][3].y)));
        mx = warpMax(mx);   // warp == full 256-col row
        float h  = 0.5f * ((i & 1) ? hacc[i >> 1].y : hacc[i >> 1].x);
        float hm = h + mx;
        float4 o0, o1;
        if (ISQ) {
            o0.x = (__expf(acc[i][0].x - hm) + EPS_PHI) * INV_SQRT_M;
            o0.y = (__expf(acc[i][0].y - hm) + EPS_PHI) * INV_SQRT_M;
            o0.z = (__expf(acc[i][1].x - hm) + EPS_PHI) * INV_SQRT_M;
            o0.w = (__expf(acc[i][1].y - hm) + EPS_PHI) * INV_SQRT_M;
            o1.x = (__expf(acc[i][2].x - hm) + EPS_PHI) * INV_SQRT_M;
            o1.y = (__expf(acc[i][2].y - hm) + EPS_PHI) * INV_SQRT_M;
            o1.z = (__expf(acc[i][3].x - hm) + EPS_PHI) * INV_SQRT_M;
            o1.w = (__expf(acc[i][3].y - hm) + EPS_PHI) * INV_SQRT_M;
        } else {
            // Kp0 = exp(U - h - rowmax); eps/scale applied after segmax is known
            o0.x = __expf(acc[i][0].x - hm);
            o0.y = __expf(acc[i][0].y - hm);
            o0.z = __expf(acc[i][1].x - hm);
            o0.w = __expf(acc[i][1].y - hm);
            o1.x = __expf(acc[i][2].x - hm);
            o1.y = __expf(acc[i][2].y - hm);
            o1.z = __expf(acc[i][3].x - hm);
            o1.w = __expf(acc[i][3].y - hm);
            if (tx == 0) g_rowmax[row] = mx;
            blockmax = fmaxf(blockmax, mx);
        }
        *(float4*)(Out + (size_t)row * MF + tx * 4)       = o0;
        *(float4*)(Out + (size_t)row * MF + 128 + tx * 4) = o1;
    }
    if (!ISQ) {
        if (tx == 0) s_wmax[ty] = blockmax;
        __syncthreads();
        if (tid == 0) {
            float bm = s_wmax[0];
#pragma unroll
            for (int w = 1; w < 8; w++) bm = fmaxf(bm, s_wmax[w]);
            atomicMax(&g_segmax[row0 >> 9], f2o(bm));  // 64 rows per block share a segment
        }
    }
}

// ---------------- rescale K: Kp = (Kp0 * exp(rowmax - segmax) + eps)/sqrt(m) ----------------
__global__ __launch_bounds__(512)
void scalek_kernel()
{
    int idx = blockIdx.x * 512 + threadIdx.x;   // float4 index, 2,097,152 total
    int row = idx >> 6;
    float s = __expf(g_rowmax[row] - o2f(g_segmax[row >> 9]));
    float4 v = *(float4*)(g_Kp + (size_t)idx * 4);
    v.x = (v.x * s + EPS_PHI) * INV_SQRT_M;
    v.y = (v.y * s + EPS_PHI) * INV_SQRT_M;
    v.z = (v.z * s + EPS_PHI) * INV_SQRT_M;
    v.w = (v.w * s + EPS_PHI) * INV_SQRT_M;
    *(float4*)(g_Kp + (size_t)idx * 4) = v;
}

// ---------------- Ksum partials (deterministic, 4 per batch) ----------------
__global__ __launch_bounds__(256)
void ksum_kernel()
{
    int b = blockIdx.x, p = blockIdx.y, j = threadIdx.x;
    const float* Kp = g_Kp + ((size_t)b * NPER + p * 128) * MF + j;
    float s0 = 0.f, s1 = 0.f, s2 = 0.f, s3 = 0.f;
#pragma unroll 4
    for (int n = 0; n < 128; n += 4) {
        s0 += Kp[(n + 0) * MF];
        s1 += Kp[(n + 1) * MF];
        s2 += Kp[(n + 2) * MF];
        s3 += Kp[(n + 3) * MF];
    }
    g_KsumP[(b * 4 + p) * MF + j] = (s0 + s1) + (s2 + s3);
}

// ---------------- KV = Kp_b^T @ V_b : per block 64(m) x 256(v), K over n=512 ----------------
__global__ __launch_bounds__(256)
void kv_kernel(const float* __restrict__ V)
{
    __shared__ float As[32 * 64];    // [n][mm]
    __shared__ float Bs[32 * 256];   // [n][vv]
    const int tid = threadIdx.x;
    const int ty  = tid >> 5;
    const int tx  = tid & 31;
    const int b   = blockIdx.x >> 2;
    const int mm0 = (blockIdx.x & 3) * 64;
    const float* Kp = g_Kp + (size_t)b * NPER * MF;
    const float* Vb = V + (size_t)b * NPER * DV;

    float2 acc[8][4];
#pragma unroll
    for (int i = 0; i < 8; i++)
#pragma unroll
        for (int g = 0; g < 4; g++) acc[i][g] = make_float2(0.f, 0.f);

    for (int n0 = 0; n0 < NPER; n0 += 32) {
#pragma unroll
        for (int s = 0; s < 2; s++) {
            int idx = tid + s * 256;
            int r = idx >> 4, c4 = idx & 15;
            *(float4*)(As + r * 64 + c4 * 4) =
                *(const float4*)(Kp + (size_t)(n0 + r) * MF + mm0 + c4 * 4);
        }
#pragma unroll
        for (int s = 0; s < 8; s++) {
            int idx = tid + s * 256;
            int r = idx >> 6, c4 = idx & 63;
            *(float4*)(Bs + r * 256 + c4 * 4) =
                *(const float4*)(Vb + (size_t)(n0 + r) * DV + c4 * 4);
        }
        __syncthreads();
#pragma unroll 4
        for (int kk = 0; kk < 32; kk++) {
            float a[8];
#pragma unroll
            for (int i = 0; i < 8; i++) a[i] = As[kk * 64 + ty * 8 + i];
            float4 b0 = *(const float4*)(Bs + kk * 256 + tx * 4);
            float4 b1 = *(const float4*)(Bs + kk * 256 + 128 + tx * 4);
#pragma unroll
            for (int i = 0; i < 8; i++) {
                float2 aa = make_float2(a[i], a[i]);
                ffma2(acc[i][0], aa, make_float2(b0.x, b0.y));
                ffma2(acc[i][1], aa, make_float2(b0.z, b0.w));
                ffma2(acc[i][2], aa, make_float2(b1.x, b1.y));
                ffma2(acc[i][3], aa, make_float2(b1.z, b1.w));
            }
        }
        __syncthreads();
    }

    float* C = g_KV + (size_t)b * MF * DV;
#pragma unroll
    for (int i = 0; i < 8; i++) {
        int mm = mm0 + ty * 8 + i;
        float4 o0 = make_float4(acc[i][0].x, acc[i][0].y, acc[i][1].x, acc[i][1].y);
        float4 o1 = make_float4(acc[i][2].x, acc[i][2].y, acc[i][3].x, acc[i][3].y);
        *(float4*)(C + (size_t)mm * DV + tx * 4)       = o0;
        *(float4*)(C + (size_t)mm * DV + 128 + tx * 4) = o1;
    }
}

// ---------------- norm[i] = Qp[i] . Ksum[seg(i)] + eps (warp per row) ----------------
__global__ __launch_bounds__(256)
void norm_kernel()
{
    const int tid = threadIdx.x;
    const int ty  = tid >> 5;
    const int tx  = tid & 31;
    const int row = blockIdx.x * 8 + ty;
    const int b   = row >> 9;
    const float* P = g_KsumP + (size_t)b * 4 * MF;

    float4 q0 = *(const float4*)(g_Qp + (size_t)row * MF + tx * 4);
    float4 q1 = *(const float4*)(g_Qp + (size_t)row * MF + 128 + tx * 4);
    float4 k0 = make_float4(0.f, 0.f, 0.f, 0.f), k1 = k0;
#pragma unroll
    for (int p = 0; p < 4; p++) {
        float4 a = *(const float4*)(P + p * MF + tx * 4);
        float4 c = *(const float4*)(P + p * MF + 128 + tx * 4);
        k0.x += a.x; k0.y += a.y; k0.z += a.z; k0.w += a.w;
        k1.x += c.x; k1.y += c.y; k1.z += c.z; k1.w += c.w;
    }
    float dot = q0.x * k0.x + q0.y * k0.y + q0.z * k0.z + q0.w * k0.w
              + q1.x * k1.x + q1.y * k1.y + q1.z * k1.z + q1.w * k1.w;
    dot = warpSum(dot);
    if (tx == 0) g_norm[row] = dot + EPS_NORM;
}

// ---------------- out = (Qp_b @ KV_b) / norm : per block 64 rows x 256 cols ----------------
__global__ __launch_bounds__(256)
void out_kernel(float* __restrict__ Out)
{
    __shared__ float As[64 * 32];    // [r][k]
    __shared__ float Bs[32 * 256];   // [k][vv]
    const int tid = threadIdx.x;
    const int ty  = tid >> 5;
    const int tx  = tid & 31;
    const int b   = blockIdx.x >> 3;
    const int row0 = b * NPER + (blockIdx.x & 7) * 64;
    const float* KV = g_KV + (size_t)b * MF * DV;

    float2 acc[8][4];
#pragma unroll
    for (int i = 0; i < 8; i++)
#pragma unroll
        for (int g = 0; g < 4; g++) acc[i][g] = make_float2(0.f, 0.f);

    for (int k0 = 0; k0 < MF; k0 += 32) {
#pragma unroll
        for (int s = 0; s < 2; s++) {
            int idx = tid + s * 256;
            int r = idx >> 3, c4 = idx & 7;
            *(float4*)(As + r * 32 + c4 * 4) =
                *(const float4*)(g_Qp + (size_t)(row0 + r) * MF + k0 + c4 * 4);
        }
#pragma unroll
        for (int s = 0; s < 8; s++) {
            int idx = tid + s * 256;
            int r = idx >> 6, c4 = idx & 63;
            *(float4*)(Bs + r * 256 + c4 * 4) =
                *(const float4*)(KV + (size_t)(k0 + r) * DV + c4 * 4);
        }
        __syncthreads();
#pragma unroll 4
        for (int kk = 0; kk < 32; kk++) {
            float a[8];
#pragma unroll
            for (int i = 0; i < 8; i++) a[i] = As[(ty * 8 + i) * 32 + kk];
            float4 b0 = *(const float4*)(Bs + kk * 256 + tx * 4);
            float4 b1 = *(const float4*)(Bs + kk * 256 + 128 + tx * 4);
#pragma unroll
            for (int i = 0; i < 8; i++) {
                float2 aa = make_float2(a[i], a[i]);
                ffma2(acc[i][0], aa, make_float2(b0.x, b0.y));
                ffma2(acc[i][1], aa, make_float2(b0.z, b0.w));
                ffma2(acc[i][2], aa, make_float2(b1.x, b1.y));
                ffma2(acc[i][3], aa, make_float2(b1.z, b1.w));
            }
        }
        __syncthreads();
    }

#pragma unroll
    for (int i = 0; i < 8; i++) {
        int row = row0 + ty * 8 + i;
        float inv = 1.0f / g_norm[row];
        float4 o0 = make_float4(acc[i][0].x * inv, acc[i][0].y * inv,
                                acc[i][1].x * inv, acc[i][1].y * inv);
        float4 o1 = make_float4(acc[i][2].x * inv, acc[i][2].y * inv,
                                acc[i][3].x * inv, acc[i][3].y * inv);
        *(float4*)(Out + (size_t)row * DV + tx * 4)       = o0;
        *(float4*)(Out + (size_t)row * DV + 128 + tx * 4) = o1;
    }
}

// ---------------- launch ----------------
extern "C" void kernel_launch(void* const* d_in, const int* in_sizes, int n_in,
                              void* d_out, int out_size)
{
    (void)in_sizes; (void)n_in; (void)out_size;
    const float* Q     = (const float*)d_in[0];
    const float* K     = (const float*)d_in[1];
    const float* V     = (const float*)d_in[2];
    const float* omega = (const float*)d_in[3];
    float* Out = (float*)d_out;

    init_kernel<<<1, 64>>>();
    phi_kernel<1><<<N_TOK / 64, 256>>>(Q, omega);
    phi_kernel<0><<<N_TOK / 64, 256>>>(K, omega);
    scalek_kernel<<<(N_TOK * MF / 4) / 512, 512>>>();
    ksum_kernel<<<dim3(NBATCH, 4), 256>>>();
    kv_kernel<<<NBATCH * 4, 256>>>(V);
    norm_kernel<<<N_TOK / 8, 256>>>();
    out_kernel<<<NBATCH * 8, 256>>>(Out);
}